// round 1
// baseline (speedup 1.0000x reference)
#include <cuda_runtime.h>
#include <math.h>

#define BB   64
#define TT   256
#define OBSD 512
#define ACTD 32
#define LATD 64
#define TA   255          // T-1
#define NBT  (BB*TA)      // 16320
#define PHID 512

// output offsets (floats)
#define OFF_RHO (BB*TT*LATD)                      // 1,048,576
#define RHO_SZ  ((size_t)NBT*LATD*LATD)           // 66,846,720
#define OFF_PL  (OFF_RHO + RHO_SZ)                // 67,895,296
#define OFF_PO  (OFF_PL + (size_t)BB*TT*LATD)     // 68,943,872

// ---------------------------------------------------------------------------
// Generic tiled GEMM: C[M,N] = A[M,K] @ W[K,N] + bias, row-major fp32.
// BM=128, BN=64, BK=32, 256 threads, thread tile 8x4.
// ---------------------------------------------------------------------------
__global__ __launch_bounds__(256) void gemm_bias_kernel(
    const float* __restrict__ A, const float* __restrict__ W,
    const float* __restrict__ bias, float* __restrict__ C,
    int M, int N, int K)
{
    __shared__ float As[32][128];   // transposed: As[k][m]
    __shared__ float Ws[32][64];    // Ws[k][n]

    int tid = threadIdx.x;
    int rowBase = blockIdx.y * 128;
    int colBase = blockIdx.x * 64;
    int ty = tid >> 4, tx = tid & 15;

    float acc[8][4];
#pragma unroll
    for (int i = 0; i < 8; i++)
#pragma unroll
        for (int j = 0; j < 4; j++) acc[i][j] = 0.f;

    for (int kt = 0; kt < K; kt += 32) {
        __syncthreads();
#pragma unroll
        for (int p = 0; p < 4; p++) {
            int v = p * 256 + tid;
            int m = v >> 3, c4 = v & 7;
            float4 a = *(const float4*)&A[(size_t)(rowBase + m) * K + kt + c4 * 4];
            As[c4 * 4 + 0][m] = a.x;
            As[c4 * 4 + 1][m] = a.y;
            As[c4 * 4 + 2][m] = a.z;
            As[c4 * 4 + 3][m] = a.w;
        }
#pragma unroll
        for (int p = 0; p < 2; p++) {
            int v = p * 256 + tid;
            int r = v >> 4, c4 = v & 15;
            *(float4*)&Ws[r][c4 * 4] =
                *(const float4*)&W[(size_t)(kt + r) * N + colBase + c4 * 4];
        }
        __syncthreads();
#pragma unroll
        for (int kk = 0; kk < 32; kk++) {
            float4 a0 = *(const float4*)&As[kk][ty * 8];
            float4 a1 = *(const float4*)&As[kk][ty * 8 + 4];
            float4 w  = *(const float4*)&Ws[kk][tx * 4];
            float av[8] = {a0.x, a0.y, a0.z, a0.w, a1.x, a1.y, a1.z, a1.w};
            float wv[4] = {w.x, w.y, w.z, w.w};
#pragma unroll
            for (int i = 0; i < 8; i++)
#pragma unroll
                for (int j = 0; j < 4; j++)
                    acc[i][j] = fmaf(av[i], wv[j], acc[i][j]);
        }
    }

    float4 bv = *(const float4*)&bias[colBase + tx * 4];
#pragma unroll
    for (int i = 0; i < 8; i++) {
        float4 o;
        o.x = acc[i][0] + bv.x;
        o.y = acc[i][1] + bv.y;
        o.z = acc[i][2] + bv.z;
        o.w = acc[i][3] + bv.w;
        *(float4*)&C[(size_t)(rowBase + ty * 8 + i) * N + colBase + tx * 4] = o;
    }
}

// ---------------------------------------------------------------------------
// 8x8 matmul, fully unrolled, register-resident.
// ---------------------------------------------------------------------------
__device__ __forceinline__ void mm8(float* Tt, const float* Bm, const float* Sm)
{
#pragma unroll
    for (int i = 0; i < 8; i++) {
#pragma unroll
        for (int jj = 0; jj < 8; jj++) {
            float acc = Bm[i * 8 + 0] * Sm[0 * 8 + jj];
#pragma unroll
            for (int m = 1; m < 8; m++)
                acc = fmaf(Bm[i * 8 + m], Sm[m * 8 + jj], acc);
            Tt[i * 8 + jj] = acc;
        }
    }
}

// ---------------------------------------------------------------------------
// Fused: after_phi = actions @ W_phi + b_phi, per-block expm (of transposed
// 8x8 block) via scaling+squaring + Taylor-6 Horner, write block-diagonal
// rho tile (blocks + zeros).  16 (b,t) pairs per CTA, one thread per block.
// ---------------------------------------------------------------------------
#define K2_PAIRS 16
#define K2_SMEM  ((ACTD*PHID + K2_PAIRS*ACTD) * 4)

__global__ __launch_bounds__(128, 2) void phi_expm_kernel(
    const float* __restrict__ actions, const float* __restrict__ Wphi,
    const float* __restrict__ bphi, float* __restrict__ rho)
{
    extern __shared__ float smem[];
    float* sWp  = smem;                 // 32*512 floats, f4-swizzled
    float* sAct = smem + ACTD * PHID;   // 16*32 floats

    int tid = threadIdx.x;
    int bt0 = blockIdx.x * K2_PAIRS;

    // stage W_phi (swizzled on float4 granularity to kill k-stride conflicts)
    {
        const float4* src = (const float4*)Wphi;
        float4* dst = (float4*)sWp;
#pragma unroll
        for (int n = 0; n < 32; n++) {          // 4096 f4 / 128 threads
            int v = n * 128 + tid;
            int r = v >> 7, q = v & 127;
            dst[r * 128 + (q ^ ((q >> 4) & 7))] = src[v];
        }
    }
    // stage actions for our 16 pairs (512 floats = 128 f4)
    {
        const float4* src = (const float4*)(actions + (size_t)bt0 * ACTD);
        ((float4*)sAct)[tid] = src[tid];
    }
    __syncthreads();

    int p  = tid >> 3;          // pair 0..15
    int kb = tid & 7;           // block 0..7
    int bt = bt0 + p;

    // ---- phi block: Am[8x+y] = P[x][y] -------------------------------------
    float Am[64];
#pragma unroll
    for (int u = 0; u < 16; u++) {
        float4 bb = ((const float4*)bphi)[kb * 16 + u];
        Am[4 * u + 0] = bb.x; Am[4 * u + 1] = bb.y;
        Am[4 * u + 2] = bb.z; Am[4 * u + 3] = bb.w;
    }
    const float4* sWp4 = (const float4*)sWp;
#pragma unroll
    for (int r = 0; r < 32; r++) {
        float a = sAct[p * 32 + r];
#pragma unroll
        for (int u = 0; u < 16; u++) {
            int q = kb * 16 + u;
            float4 w = sWp4[r * 128 + (q ^ ((q >> 4) & 7))];
            Am[4 * u + 0] = fmaf(a, w.x, Am[4 * u + 0]);
            Am[4 * u + 1] = fmaf(a, w.y, Am[4 * u + 1]);
            Am[4 * u + 2] = fmaf(a, w.z, Am[4 * u + 2]);
            Am[4 * u + 3] = fmaf(a, w.w, Am[4 * u + 3]);
        }
    }

    // ---- scaling: ||P||_inf / 2^s <= 0.25 ----------------------------------
    float nrm = 0.f;
#pragma unroll
    for (int i = 0; i < 8; i++) {
        float rs = 0.f;
#pragma unroll
        for (int jj = 0; jj < 8; jj++) rs += fabsf(Am[i * 8 + jj]);
        nrm = fmaxf(nrm, rs);
    }
    int s = 0;
    if (nrm > 0.25f) {
        s = (int)ceilf(log2f(nrm * 4.0f));
        if (s < 0) s = 0;
        if (s > 12) s = 12;
    }
    float sc = exp2f((float)(-s));
#pragma unroll
    for (int d = 0; d < 64; d++) Am[d] *= sc;

    // ---- Taylor order 6, Horner: S = I + B/6; S = I + (B*S)/c, c=5..1 ------
    float S[64], Tt[64];
#pragma unroll
    for (int d = 0; d < 64; d++)
        S[d] = Am[d] * (1.0f / 6.0f) + ((d % 9 == 0) ? 1.0f : 0.0f);
    const float invc[5] = {0.2f, 0.25f, 1.0f / 3.0f, 0.5f, 1.0f};
#pragma unroll
    for (int c = 0; c < 5; c++) {
        mm8(Tt, Am, S);
#pragma unroll
        for (int d = 0; d < 64; d++)
            S[d] = Tt[d] * invc[c] + ((d % 9 == 0) ? 1.0f : 0.0f);
    }
    // ---- squarings ----------------------------------------------------------
    for (int q = 0; q < s; q++) {
        mm8(Tt, S, S);
#pragma unroll
        for (int d = 0; d < 64; d++) S[d] = Tt[d];
    }

    // ---- write diagonal block: M[i][j] = exp(P^T)[i][j] = S[j*8+i] ---------
    float* dstb = rho + (size_t)bt * (LATD * LATD) + (size_t)(kb * 8) * LATD + kb * 8;
#pragma unroll
    for (int i = 0; i < 8; i++) {
        float4 v0 = make_float4(S[0 * 8 + i], S[1 * 8 + i], S[2 * 8 + i], S[3 * 8 + i]);
        float4 v1 = make_float4(S[4 * 8 + i], S[5 * 8 + i], S[6 * 8 + i], S[7 * 8 + i]);
        *(float4*)&dstb[(size_t)i * LATD]     = v0;
        *(float4*)&dstb[(size_t)i * LATD + 4] = v1;
    }

    // ---- write zeros everywhere else (disjoint bytes, no sync needed) ------
    float4 z = make_float4(0.f, 0.f, 0.f, 0.f);
    float4* dz = (float4*)(rho + (size_t)bt0 * (LATD * LATD));
    for (int f = tid; f < K2_PAIRS * 1024; f += 128) {
        int rem = f & 1023;
        int row = rem >> 4, c4 = rem & 15;
        if ((c4 >> 1) != (row >> 3)) dz[f] = z;
    }
}

// ---------------------------------------------------------------------------
// Sequential scan: h_{t+1} = h_t @ rho_t, block-diagonal => 512 independent
// 8-dim chains.  8 threads per chain (thread j holds column j of M),
// h broadcast via shfl.  Prefetch distance 4 hides L2 latency.
// ---------------------------------------------------------------------------
__global__ __launch_bounds__(64) void scan_kernel(
    const float* __restrict__ latent, const float* __restrict__ rho,
    float* __restrict__ predLat)
{
    int b   = blockIdx.x;
    int sub = threadIdx.x;          // 0..63
    int kb  = sub >> 3, j = sub & 7;
    int grp = (sub & 31) & 24;      // 8-lane group base within warp

    const float* mbase = rho + (size_t)b * TA * (LATD * LATD)
                             + (size_t)(kb * 8) * LATD + kb * 8 + j;
    float h = latent[(size_t)b * TT * LATD + sub];
    predLat[(size_t)b * TT * LATD + sub] = h;

    float b0[8], b1[8], b2[8], b3[8];

#define LDBUF(buf, t) { const float* pp = mbase + (size_t)(t) * (LATD*LATD); \
    _Pragma("unroll") for (int i = 0; i < 8; i++) buf[i] = pp[(size_t)i * LATD]; }

#define STEPH(buf, t) { float hn = 0.f; \
    _Pragma("unroll") for (int i = 0; i < 8; i++) { \
        float hv = __shfl_sync(0xffffffffu, h, grp + i); \
        hn = fmaf(hv, buf[i], hn); } \
    h = hn; \
    predLat[(size_t)(b * TT + (t) + 1) * LATD + sub] = h; }

    LDBUF(b0, 0); LDBUF(b1, 1); LDBUF(b2, 2); LDBUF(b3, 3);
    int t = 0;
    for (int it = 0; it < 62; it++) {
        STEPH(b0, t); LDBUF(b0, t + 4); t++;
        STEPH(b1, t); LDBUF(b1, t + 4); t++;
        STEPH(b2, t); LDBUF(b2, t + 4); t++;
        STEPH(b3, t); LDBUF(b3, t + 4); t++;
    }
    // t = 248; buffers hold 248..251
    STEPH(b0, 248); LDBUF(b0, 252);
    STEPH(b1, 249); LDBUF(b1, 253);
    STEPH(b2, 250); LDBUF(b2, 254);
    STEPH(b3, 251);
    STEPH(b0, 252);
    STEPH(b1, 253);
    STEPH(b2, 254);
#undef LDBUF
#undef STEPH
}

// ---------------------------------------------------------------------------
extern "C" void kernel_launch(void* const* d_in, const int* in_sizes, int n_in,
                              void* d_out, int out_size)
{
    (void)in_sizes; (void)n_in; (void)out_size;
    const float* obs  = (const float*)d_in[0];
    const float* acts = (const float*)d_in[1];
    const float* Wenc = (const float*)d_in[2];
    const float* benc = (const float*)d_in[3];
    const float* Wdec = (const float*)d_in[4];
    const float* bdec = (const float*)d_in[5];
    const float* Wphi = (const float*)d_in[6];
    const float* bphi = (const float*)d_in[7];

    float* out    = (float*)d_out;
    float* latent = out;
    float* rho    = out + OFF_RHO;
    float* predL  = out + OFF_PL;
    float* predO  = out + OFF_PO;

    cudaFuncSetAttribute(phi_expm_kernel,
                         cudaFuncAttributeMaxDynamicSharedMemorySize, K2_SMEM);

    // 1. latent_obs = obs @ W_enc + b_enc   (16384 x 64, K=512)
    gemm_bias_kernel<<<dim3(1, 128), 256>>>(obs, Wenc, benc, latent,
                                            BB * TT, LATD, OBSD);
    // 2. rho (phi GEMM + expm + block-diagonal emit)
    phi_expm_kernel<<<NBT / K2_PAIRS, 128, K2_SMEM>>>(acts, Wphi, bphi, rho);
    // 3. sequential latent scan
    scan_kernel<<<BB, 64>>>(latent, rho, predL);
    // 4. predicted_obs = predL @ W_dec + b_dec  (16384 x 512, K=64)
    gemm_bias_kernel<<<dim3(8, 128), 256>>>(predL, Wdec, bdec, predO,
                                            BB * TT, PHID, LATD);
}

// round 3
// speedup vs baseline: 1.1100x; 1.1100x over previous
#include <cuda_runtime.h>
#include <math.h>

#define BB   64
#define TT   256
#define OBSD 512
#define ACTD 32
#define LATD 64
#define TA   255          // T-1
#define NBT  (BB*TA)      // 16320
#define PHID 512

// output offsets (floats)
#define OFF_RHO (BB*TT*LATD)                      // 1,048,576
#define RHO_SZ  ((size_t)NBT*LATD*LATD)           // 66,846,720
#define OFF_PL  (OFF_RHO + RHO_SZ)                // 67,895,296
#define OFF_PO  (OFF_PL + (size_t)BB*TT*LATD)     // 68,943,872

typedef unsigned long long ull;

// compact block scratch for the scan: [bt][kb][i][j]
__device__ float g_compact[(size_t)NBT * 512];

// ---------------------------------------------------------------------------
// packed f32x2 helpers (sm_103a)
// ---------------------------------------------------------------------------
__device__ __forceinline__ ull pk2(float lo, float hi) {
    ull r; asm("mov.b64 %0, {%1, %2};" : "=l"(r) : "f"(lo), "f"(hi)); return r;
}
__device__ __forceinline__ void upk2(float& lo, float& hi, ull v) {
    asm("mov.b64 {%0, %1}, %2;" : "=f"(lo), "=f"(hi) : "l"(v));
}
__device__ __forceinline__ ull fma2(ull a, ull b, ull c) {
    ull d; asm("fma.rn.f32x2 %0, %1, %2, %3;" : "=l"(d) : "l"(a), "l"(b), "l"(c)); return d;
}
__device__ __forceinline__ ull mul2(ull a, ull b) {
    ull d; asm("mul.rn.f32x2 %0, %1, %2;" : "=l"(d) : "l"(a), "l"(b)); return d;
}
__device__ __forceinline__ ull add2(ull a, ull b) {
    ull d; asm("add.rn.f32x2 %0, %1, %2;" : "=l"(d) : "l"(a), "l"(b)); return d;
}

// ---------------------------------------------------------------------------
// GEMM: C[M,N] = A[M,K] @ W[K,N] + bias.  BM=128 BN=64 BK=32, 256 threads,
// per-thread 4 rows x 8 cols, f32x2 accumulators (FFMA2).
// ---------------------------------------------------------------------------
__global__ __launch_bounds__(256) void gemm_bias_kernel(
    const float* __restrict__ A, const float* __restrict__ W,
    const float* __restrict__ bias, float* __restrict__ C,
    int M, int N, int K)
{
    __shared__ float As[32][132];   // transposed: As[k][m], padded
    __shared__ float Ws[32][68];    // Ws[k][n], padded

    int tid = threadIdx.x;
    int rowBase = blockIdx.y * 128;
    int colBase = blockIdx.x * 64;
    int ty = tid >> 3;      // 0..31 -> rows ty*4
    int tx = tid & 7;       // 0..7  -> cols tx*8

    ull acc2[4][4];
#pragma unroll
    for (int i = 0; i < 4; i++)
#pragma unroll
        for (int jp = 0; jp < 4; jp++) acc2[i][jp] = 0ull;

    for (int kt = 0; kt < K; kt += 32) {
        __syncthreads();
#pragma unroll
        for (int n = 0; n < 4; n++) {
            int v = n * 256 + tid;
            int m = v >> 3, c4 = v & 7;
            float4 a = *(const float4*)&A[(size_t)(rowBase + m) * K + kt + c4 * 4];
            As[c4 * 4 + 0][m] = a.x;
            As[c4 * 4 + 1][m] = a.y;
            As[c4 * 4 + 2][m] = a.z;
            As[c4 * 4 + 3][m] = a.w;
        }
#pragma unroll
        for (int n = 0; n < 2; n++) {
            int v = n * 256 + tid;
            int r = v >> 4, c4 = v & 15;
            *(float4*)&Ws[r][c4 * 4] =
                *(const float4*)&W[(size_t)(kt + r) * N + colBase + c4 * 4];
        }
        __syncthreads();
#pragma unroll
        for (int kk = 0; kk < 32; kk++) {
            float4 av = *(const float4*)&As[kk][ty * 4];
            ulonglong2 w0 = *(const ulonglong2*)&Ws[kk][tx * 8];
            ulonglong2 w1 = *(const ulonglong2*)&Ws[kk][tx * 8 + 4];
            float a4[4] = {av.x, av.y, av.z, av.w};
#pragma unroll
            for (int i = 0; i < 4; i++) {
                ull ad = pk2(a4[i], a4[i]);
                acc2[i][0] = fma2(ad, w0.x, acc2[i][0]);
                acc2[i][1] = fma2(ad, w0.y, acc2[i][1]);
                acc2[i][2] = fma2(ad, w1.x, acc2[i][2]);
                acc2[i][3] = fma2(ad, w1.y, acc2[i][3]);
            }
        }
    }

    ulonglong2 b0 = *(const ulonglong2*)&bias[colBase + tx * 8];
    ulonglong2 b1 = *(const ulonglong2*)&bias[colBase + tx * 8 + 4];
#pragma unroll
    for (int i = 0; i < 4; i++) {
        float* dst = &C[(size_t)(rowBase + ty * 4 + i) * N + colBase + tx * 8];
        ulonglong2 o0, o1;
        o0.x = add2(acc2[i][0], b0.x);
        o0.y = add2(acc2[i][1], b0.y);
        o1.x = add2(acc2[i][2], b1.x);
        o1.y = add2(acc2[i][3], b1.y);
        *(ulonglong2*)dst       = o0;
        *(ulonglong2*)(dst + 4) = o1;
    }
}

// ---------------------------------------------------------------------------
// distributed 8x8 matmul: 2 threads per matrix, each owns 4 rows packed f32x2.
// T2 = B * S ;  rows of S fetched from partner via shfl_xor(1).
// ---------------------------------------------------------------------------
__device__ __forceinline__ void mm8h(ull T2[4][4], const ull B2[4][4],
                                     const ull S2[4][4], int h)
{
#pragma unroll
    for (int i = 0; i < 4; i++)
#pragma unroll
        for (int jp = 0; jp < 4; jp++) T2[i][jp] = 0ull;

#pragma unroll
    for (int m = 0; m < 8; m++) {
        int lr = m & 3;
        ull row[4];
#pragma unroll
        for (int jp = 0; jp < 4; jp++) {
            ull v = S2[lr][jp];
            ull o = __shfl_xor_sync(0xffffffffu, v, 1);
            row[jp] = ((m >> 2) == h) ? v : o;
        }
#pragma unroll
        for (int i = 0; i < 4; i++) {
            float blo, bhi; upk2(blo, bhi, B2[i][m >> 1]);
            float b = (m & 1) ? bhi : blo;
            ull bd = pk2(b, b);
#pragma unroll
            for (int jp = 0; jp < 4; jp++)
                T2[i][jp] = fma2(bd, row[jp], T2[i][jp]);
        }
    }
}

// add identity to my 4 rows (global rows 4h+i, diag col = 4h+i)
__device__ __forceinline__ void addI(ull S2[4][4], int h)
{
    if (h == 0) {
#pragma unroll
        for (int i = 0; i < 4; i++) {
            float lo, hi; upk2(lo, hi, S2[i][i >> 1]);
            if (i & 1) hi += 1.f; else lo += 1.f;
            S2[i][i >> 1] = pk2(lo, hi);
        }
    } else {
#pragma unroll
        for (int i = 0; i < 4; i++) {
            float lo, hi; upk2(lo, hi, S2[i][2 + (i >> 1)]);
            if (i & 1) hi += 1.f; else lo += 1.f;
            S2[i][2 + (i >> 1)] = pk2(lo, hi);
        }
    }
}

// ---------------------------------------------------------------------------
// Fused phi GEMM + per-block expm + block-diagonal rho emit (+ compact copy).
// 8 (b,t) pairs per CTA; 2 threads per 8x8 block (each owns 4 rows).
// ---------------------------------------------------------------------------
#define P_PAIRS 8
#define P_SMEM  ((ACTD*PHID + P_PAIRS*ACTD) * 4)
#define SWZ(q)  ((q) ^ (((q) >> 3) & 7))

__global__ __launch_bounds__(128, 3) void phi_expm_kernel(
    const float* __restrict__ actions, const float* __restrict__ Wphi,
    const float* __restrict__ bphi, float* __restrict__ rho)
{
    extern __shared__ float smem[];
    float* sWp  = smem;                 // 32*512 floats, f4-swizzled
    float* sAct = smem + ACTD * PHID;   // 8*32 floats

    int tid = threadIdx.x;
    int bt0 = blockIdx.x * P_PAIRS;

    // stage W_phi swizzled
    {
        const float4* src = (const float4*)Wphi;
        float4* dst = (float4*)sWp;
#pragma unroll
        for (int n = 0; n < 32; n++) {
            int v = n * 128 + tid;
            dst[(v >> 7) * 128 + SWZ(v & 127)] = src[v];
        }
    }
    if (tid < 64)
        ((float4*)sAct)[tid] = ((const float4*)(actions + (size_t)bt0 * ACTD))[tid];
    __syncthreads();

    int p  = tid >> 4;          // pair 0..7
    int kb = (tid >> 1) & 7;    // block 0..7
    int h  = tid & 1;           // row-half 0/1 (partner = lane^1)
    int bt = bt0 + p;

    const float4* sWp4 = (const float4*)sWp;

    // ---- phi: my rows x = 4h+i of block kb (P[x][y] = after_phi[kb*64+8x+y])
    ull A2[4][4];
#pragma unroll
    for (int i = 0; i < 4; i++) {
        int q0 = kb * 16 + 8 * h + 2 * i;
        ulonglong2 bb0 = *(const ulonglong2*)((const float4*)bphi + q0);
        ulonglong2 bb1 = *(const ulonglong2*)((const float4*)bphi + q0 + 1);
        A2[i][0] = bb0.x; A2[i][1] = bb0.y;
        A2[i][2] = bb1.x; A2[i][3] = bb1.y;
    }
#pragma unroll
    for (int r = 0; r < 32; r++) {
        float a = sAct[p * 32 + r];
        ull ad = pk2(a, a);
#pragma unroll
        for (int i = 0; i < 4; i++) {
            int q0 = kb * 16 + 8 * h + 2 * i;
            ulonglong2 w0 = *(const ulonglong2*)(sWp4 + r * 128 + SWZ(q0));
            ulonglong2 w1 = *(const ulonglong2*)(sWp4 + r * 128 + SWZ(q0 + 1));
            A2[i][0] = fma2(ad, w0.x, A2[i][0]);
            A2[i][1] = fma2(ad, w0.y, A2[i][1]);
            A2[i][2] = fma2(ad, w1.x, A2[i][2]);
            A2[i][3] = fma2(ad, w1.y, A2[i][3]);
        }
    }

    // ---- inf-norm over full matrix (combine partner halves)
    const ull ABSM = 0x7fffffff7fffffffULL;
    float nrm = 0.f;
#pragma unroll
    for (int i = 0; i < 4; i++) {
        ull s2 = A2[i][0] & ABSM;
        s2 = add2(s2, A2[i][1] & ABSM);
        s2 = add2(s2, A2[i][2] & ABSM);
        s2 = add2(s2, A2[i][3] & ABSM);
        float lo, hi; upk2(lo, hi, s2);
        nrm = fmaxf(nrm, lo + hi);
    }
    nrm = fmaxf(nrm, __shfl_xor_sync(0xffffffffu, nrm, 1));

    int s = 0;
    if (nrm > 0.25f) {
        s = (int)ceilf(log2f(nrm * 4.0f));
        if (s < 0) s = 0;
        if (s > 12) s = 12;
    }
    float sc = exp2f((float)(-s));
    ull scd = pk2(sc, sc);
#pragma unroll
    for (int i = 0; i < 4; i++)
#pragma unroll
        for (int jp = 0; jp < 4; jp++) A2[i][jp] = mul2(A2[i][jp], scd);

    // ---- Taylor-6 Horner: S = I + A/6 ; S = I + (A*S)/c, c=5..1
    ull S2[4][4], T2[4][4];
    {
        ull c6 = pk2(1.0f / 6.0f, 1.0f / 6.0f);
#pragma unroll
        for (int i = 0; i < 4; i++)
#pragma unroll
            for (int jp = 0; jp < 4; jp++) S2[i][jp] = mul2(A2[i][jp], c6);
        addI(S2, h);
    }
    const float invc[5] = {0.2f, 0.25f, 1.0f / 3.0f, 0.5f, 1.0f};
#pragma unroll
    for (int c = 0; c < 5; c++) {
        mm8h(T2, A2, S2, h);
        ull ic = pk2(invc[c], invc[c]);
#pragma unroll
        for (int i = 0; i < 4; i++)
#pragma unroll
            for (int jp = 0; jp < 4; jp++) S2[i][jp] = mul2(T2[i][jp], ic);
        addI(S2, h);
    }

    // ---- squarings (warp-uniform trip count, per-pair predicated commit)
    int smax = __reduce_max_sync(0xffffffffu, s);
    for (int q = 0; q < smax; q++) {
        mm8h(T2, S2, S2, h);
        if (q < s) {
#pragma unroll
            for (int i = 0; i < 4; i++)
#pragma unroll
                for (int jp = 0; jp < 4; jp++) S2[i][jp] = T2[i][jp];
        }
    }

    // ---- emit M = S^T : I own S rows 4h..4h+3 = M columns 4h..4h+3
    float Sf[4][8];
#pragma unroll
    for (int i = 0; i < 4; i++)
#pragma unroll
        for (int jp = 0; jp < 4; jp++)
            upk2(Sf[i][2 * jp], Sf[i][2 * jp + 1], S2[i][jp]);

    float* dstb = rho + (size_t)bt * (LATD * LATD) + (size_t)(kb * 8) * LATD + kb * 8 + 4 * h;
    float* dstc = g_compact + (size_t)bt * 512 + kb * 64 + 4 * h;
#pragma unroll
    for (int i = 0; i < 8; i++) {
        float4 v = make_float4(Sf[0][i], Sf[1][i], Sf[2][i], Sf[3][i]);
        *(float4*)&dstb[(size_t)i * LATD] = v;
        *(float4*)&dstc[i * 8]            = v;
    }

    // ---- zeros everywhere else in rho (disjoint addresses)
    float4 z = make_float4(0.f, 0.f, 0.f, 0.f);
    float4* dz = (float4*)(rho + (size_t)bt0 * (LATD * LATD));
    for (int f = tid; f < P_PAIRS * 1024; f += 128) {
        int rem = f & 1023;
        int row = rem >> 4, c4 = rem & 15;
        if ((c4 >> 1) != (row >> 3)) dz[f] = z;
    }
}

// ---------------------------------------------------------------------------
// Sequential scan over compact blocks: 512 chains of 8-dim vec-mat steps.
// 128 CTAs x 32 threads: CTA = (b, kb-half); 8 threads per chain.
// ---------------------------------------------------------------------------
__global__ __launch_bounds__(32) void scan_kernel(
    const float* __restrict__ latent, float* __restrict__ predLat)
{
    int b    = blockIdx.x >> 1;
    int half = blockIdx.x & 1;
    int sub  = threadIdx.x;          // 0..31
    int kb   = (sub >> 3) + half * 4;
    int j    = sub & 7;
    int grp  = sub & 24;
    int e    = kb * 8 + j;           // element index in 64-vector

    const float* mbase = g_compact + (size_t)b * TA * 512 + kb * 64 + j;
    float h = latent[(size_t)b * TT * LATD + e];
    predLat[(size_t)b * TT * LATD + e] = h;

    float b0[8], b1[8], b2[8], b3[8];

#define LDBUF(buf, t) { const float* pp = mbase + (size_t)(t) * 512; \
    _Pragma("unroll") for (int i = 0; i < 8; i++) buf[i] = pp[i * 8]; }

#define STEPH(buf, t) { float hn = 0.f; \
    _Pragma("unroll") for (int i = 0; i < 8; i++) { \
        float hv = __shfl_sync(0xffffffffu, h, grp + i); \
        hn = fmaf(hv, buf[i], hn); } \
    h = hn; \
    predLat[(size_t)(b * TT + (t) + 1) * LATD + e] = h; }

    LDBUF(b0, 0); LDBUF(b1, 1); LDBUF(b2, 2); LDBUF(b3, 3);
    int t = 0;
    for (int it = 0; it < 62; it++) {
        STEPH(b0, t); LDBUF(b0, t + 4); t++;
        STEPH(b1, t); LDBUF(b1, t + 4); t++;
        STEPH(b2, t); LDBUF(b2, t + 4); t++;
        STEPH(b3, t); LDBUF(b3, t + 4); t++;
    }
    STEPH(b0, 248); LDBUF(b0, 252);
    STEPH(b1, 249); LDBUF(b1, 253);
    STEPH(b2, 250); LDBUF(b2, 254);
    STEPH(b3, 251);
    STEPH(b0, 252);
    STEPH(b1, 253);
    STEPH(b2, 254);
#undef LDBUF
#undef STEPH
}

// ---------------------------------------------------------------------------
extern "C" void kernel_launch(void* const* d_in, const int* in_sizes, int n_in,
                              void* d_out, int out_size)
{
    (void)in_sizes; (void)n_in; (void)out_size;
    const float* obs  = (const float*)d_in[0];
    const float* acts = (const float*)d_in[1];
    const float* Wenc = (const float*)d_in[2];
    const float* benc = (const float*)d_in[3];
    const float* Wdec = (const float*)d_in[4];
    const float* bdec = (const float*)d_in[5];
    const float* Wphi = (const float*)d_in[6];
    const float* bphi = (const float*)d_in[7];

    float* out    = (float*)d_out;
    float* latent = out;
    float* rho    = out + OFF_RHO;
    float* predL  = out + OFF_PL;
    float* predO  = out + OFF_PO;

    cudaFuncSetAttribute(phi_expm_kernel,
                         cudaFuncAttributeMaxDynamicSharedMemorySize, P_SMEM);

    // 1. latent_obs = obs @ W_enc + b_enc   (16384 x 64, K=512)
    gemm_bias_kernel<<<dim3(1, 128), 256>>>(obs, Wenc, benc, latent,
                                            BB * TT, LATD, OBSD);
    // 2. rho blocks (phi GEMM + expm), zeros, compact scratch
    phi_expm_kernel<<<NBT / P_PAIRS, 128, P_SMEM>>>(acts, Wphi, bphi, rho);
    // 3. sequential latent scan over compact blocks
    scan_kernel<<<BB * 2, 32>>>(latent, predL);
    // 4. predicted_obs = predL @ W_dec + b_dec  (16384 x 512, K=64)
    gemm_bias_kernel<<<dim3(8, 128), 256>>>(predL, Wdec, bdec, predO,
                                            BB * TT, PHID, LATD);
}

// round 9
// speedup vs baseline: 1.3586x; 1.2240x over previous
#include <cuda_runtime.h>
#include <math.h>

#define BB   64
#define TT   256
#define OBSD 512
#define ACTD 32
#define LATD 64
#define TA   255          // T-1
#define NBT  (BB*TA)      // 16320
#define PHID 512

// output offsets (floats)
#define OFF_RHO (BB*TT*LATD)                      // 1,048,576
#define RHO_SZ  ((size_t)NBT*LATD*LATD)           // 66,846,720
#define OFF_PL  (OFF_RHO + RHO_SZ)                // 67,895,296
#define OFF_PO  (OFF_PL + (size_t)BB*TT*LATD)     // 68,943,872

typedef unsigned long long ull;

// compact block scratch for the scan: [bt][kb][i][j]
__device__ float g_compact[(size_t)NBT * 512];

// ---------------------------------------------------------------------------
// packed f32x2 helpers (sm_103a)
// ---------------------------------------------------------------------------
__device__ __forceinline__ ull pk2(float lo, float hi) {
    ull r; asm("mov.b64 %0, {%1, %2};" : "=l"(r) : "f"(lo), "f"(hi)); return r;
}
__device__ __forceinline__ void upk2(float& lo, float& hi, ull v) {
    asm("mov.b64 {%0, %1}, %2;" : "=f"(lo), "=f"(hi) : "l"(v));
}
__device__ __forceinline__ ull fma2(ull a, ull b, ull c) {
    ull d; asm("fma.rn.f32x2 %0, %1, %2, %3;" : "=l"(d) : "l"(a), "l"(b), "l"(c)); return d;
}
__device__ __forceinline__ ull mul2(ull a, ull b) {
    ull d; asm("mul.rn.f32x2 %0, %1, %2;" : "=l"(d) : "l"(a), "l"(b)); return d;
}
__device__ __forceinline__ ull add2(ull a, ull b) {
    ull d; asm("add.rn.f32x2 %0, %1, %2;" : "=l"(d) : "l"(a), "l"(b)); return d;
}

// ---------------------------------------------------------------------------
// GEMM: C[M,N] = A[M,K] @ W[K,N] + bias.  BM=128, BN templated, BK=32.
// Thread tile 8 rows x 8 cols, f32x2 accumulators: 4 LDS.128 -> 32 FFMA2/kk.
// ---------------------------------------------------------------------------
template<int BN>
__global__ __launch_bounds__(16 * (BN / 8)) void gemm_bias_kernel(
    const float* __restrict__ A, const float* __restrict__ W,
    const float* __restrict__ bias, float* __restrict__ C,
    int M, int N, int K)
{
    constexpr int T  = 16 * (BN / 8);   // threads
    constexpr int NX = BN / 8;          // threads along N

    __shared__ float As[32][132];       // transposed: As[k][m], padded
    __shared__ float Ws[32][BN + 4];    // Ws[k][n], padded (BN+4 keeps 16B align)

    int tid = threadIdx.x;
    int rowBase = blockIdx.y * 128;
    int colBase = blockIdx.x * BN;
    int ty = tid / NX;      // 0..15 -> rows ty*8
    int tx = tid % NX;      // 0..NX-1 -> cols tx*8

    ull acc[8][4];
#pragma unroll
    for (int i = 0; i < 8; i++)
#pragma unroll
        for (int jp = 0; jp < 4; jp++) acc[i][jp] = 0ull;

    for (int kt = 0; kt < K; kt += 32) {
        __syncthreads();
        // A tile: 128x32 = 1024 float4 (transpose into As[k][m])
#pragma unroll
        for (int n = 0; n < 1024 / T; n++) {
            int v = n * T + tid;
            int m = v >> 3, c4 = v & 7;
            float4 a = *(const float4*)&A[(size_t)(rowBase + m) * K + kt + c4 * 4];
            As[c4 * 4 + 0][m] = a.x;
            As[c4 * 4 + 1][m] = a.y;
            As[c4 * 4 + 2][m] = a.z;
            As[c4 * 4 + 3][m] = a.w;
        }
        // W tile: 32xBN floats = 8*BN float4
#pragma unroll
        for (int n = 0; n < (8 * BN) / T; n++) {
            int v = n * T + tid;
            int r = v / (BN / 4), c4 = v % (BN / 4);
            *(float4*)&Ws[r][c4 * 4] =
                *(const float4*)&W[(size_t)(kt + r) * N + colBase + c4 * 4];
        }
        __syncthreads();
#pragma unroll
        for (int kk = 0; kk < 32; kk++) {
            float4 a0 = *(const float4*)&As[kk][ty * 8];
            float4 a1 = *(const float4*)&As[kk][ty * 8 + 4];
            ulonglong2 w0 = *(const ulonglong2*)&Ws[kk][tx * 8];
            ulonglong2 w1 = *(const ulonglong2*)&Ws[kk][tx * 8 + 4];
            float a8[8] = {a0.x, a0.y, a0.z, a0.w, a1.x, a1.y, a1.z, a1.w};
#pragma unroll
            for (int i = 0; i < 8; i++) {
                ull ad = pk2(a8[i], a8[i]);
                acc[i][0] = fma2(ad, w0.x, acc[i][0]);
                acc[i][1] = fma2(ad, w0.y, acc[i][1]);
                acc[i][2] = fma2(ad, w1.x, acc[i][2]);
                acc[i][3] = fma2(ad, w1.y, acc[i][3]);
            }
        }
    }

    ulonglong2 b0 = *(const ulonglong2*)&bias[colBase + tx * 8];
    ulonglong2 b1 = *(const ulonglong2*)&bias[colBase + tx * 8 + 4];
#pragma unroll
    for (int i = 0; i < 8; i++) {
        float* dst = &C[(size_t)(rowBase + ty * 8 + i) * N + colBase + tx * 8];
        ulonglong2 o0, o1;
        o0.x = add2(acc[i][0], b0.x);
        o0.y = add2(acc[i][1], b0.y);
        o1.x = add2(acc[i][2], b1.x);
        o1.y = add2(acc[i][3], b1.y);
        *(ulonglong2*)dst       = o0;
        *(ulonglong2*)(dst + 4) = o1;
    }
}

// ---------------------------------------------------------------------------
// distributed 8x8 matmul: 2 threads per matrix, each owns 4 rows packed f32x2.
// T2 = B * S ;  rows of S fetched from partner via shfl_xor(1).
// ---------------------------------------------------------------------------
__device__ __forceinline__ void mm8h(ull T2[4][4], const ull B2[4][4],
                                     const ull S2[4][4], int h)
{
#pragma unroll
    for (int i = 0; i < 4; i++)
#pragma unroll
        for (int jp = 0; jp < 4; jp++) T2[i][jp] = 0ull;

#pragma unroll
    for (int m = 0; m < 8; m++) {
        int lr = m & 3;
        ull row[4];
#pragma unroll
        for (int jp = 0; jp < 4; jp++) {
            ull v = S2[lr][jp];
            ull o = __shfl_xor_sync(0xffffffffu, v, 1);
            row[jp] = ((m >> 2) == h) ? v : o;
        }
#pragma unroll
        for (int i = 0; i < 4; i++) {
            float blo, bhi; upk2(blo, bhi, B2[i][m >> 1]);
            float b = (m & 1) ? bhi : blo;
            ull bd = pk2(b, b);
#pragma unroll
            for (int jp = 0; jp < 4; jp++)
                T2[i][jp] = fma2(bd, row[jp], T2[i][jp]);
        }
    }
}

// add identity to my 4 rows (global rows 4h+i, diag col = 4h+i)
__device__ __forceinline__ void addI(ull S2[4][4], int h)
{
    if (h == 0) {
#pragma unroll
        for (int i = 0; i < 4; i++) {
            float lo, hi; upk2(lo, hi, S2[i][i >> 1]);
            if (i & 1) hi += 1.f; else lo += 1.f;
            S2[i][i >> 1] = pk2(lo, hi);
        }
    } else {
#pragma unroll
        for (int i = 0; i < 4; i++) {
            float lo, hi; upk2(lo, hi, S2[i][2 + (i >> 1)]);
            if (i & 1) hi += 1.f; else lo += 1.f;
            S2[i][2 + (i >> 1)] = pk2(lo, hi);
        }
    }
}

// ---------------------------------------------------------------------------
// Fused phi GEMM + per-block expm + block-diagonal rho emit (+ compact copy).
// kb-split: CTA = (64 (b,t) pairs, ONE kb).  Stages only the 32x64 W_phi
// slice (8.5 KB) + transposed actions (8 KB) -> ~17 KB smem, occ 4.
// 2 threads per 8x8 block (each owns 4 rows), expm math identical to before.
// ---------------------------------------------------------------------------
__global__ __launch_bounds__(128, 4) void phi_expm_kernel(
    const float* __restrict__ actions, const float* __restrict__ Wphi,
    const float* __restrict__ bphi, float* __restrict__ rho)
{
    __shared__ float sW[32][68];    // W_phi[:, kb*64 .. kb*64+63], padded pitch
    __shared__ float sAct[32][64];  // actions transposed: [r][pair]

    int tid = threadIdx.x;
    int kb  = blockIdx.y;           // 0..7
    int bt0 = blockIdx.x * 64;      // 64 pairs per CTA

    // stage W_phi slice: 512 float4 / 128 threads = 4 each
#pragma unroll
    for (int n = 0; n < 4; n++) {
        int v = n * 128 + tid;          // 0..511
        int r = v >> 4, c4 = v & 15;
        *(float4*)&sW[r][c4 * 4] =
            *((const float4*)Wphi + r * 128 + kb * 16 + c4);
    }
    // stage actions transposed: thread (p = tid>>1) loads half its pair's row
    {
        int p = tid >> 1, hh = tid & 1;
        const float4* arow = (const float4*)(actions + (size_t)(bt0 + p) * ACTD);
#pragma unroll
        for (int n = 0; n < 4; n++) {
            float4 a = arow[hh * 4 + n];
            int r = hh * 16 + n * 4;
            sAct[r + 0][p] = a.x; sAct[r + 1][p] = a.y;
            sAct[r + 2][p] = a.z; sAct[r + 3][p] = a.w;
        }
    }
    __syncthreads();

    int p  = tid >> 1;          // pair 0..63
    int h  = tid & 1;           // row-half 0/1 (partner = lane^1)
    int bt = bt0 + p;

    // ---- phi: my rows x = 4h+i of block kb (P[x][y] = after_phi[kb*64+8x+y])
    ull A2[4][4];
#pragma unroll
    for (int i = 0; i < 4; i++) {
        int q0 = kb * 16 + (4 * h + i) * 2;
        ulonglong2 bb0 = *(const ulonglong2*)((const float4*)bphi + q0);
        ulonglong2 bb1 = *(const ulonglong2*)((const float4*)bphi + q0 + 1);
        A2[i][0] = bb0.x; A2[i][1] = bb0.y;
        A2[i][2] = bb1.x; A2[i][3] = bb1.y;
    }
#pragma unroll
    for (int r = 0; r < 32; r++) {
        float a = sAct[r][p];
        ull ad = pk2(a, a);
#pragma unroll
        for (int i = 0; i < 4; i++) {
            int x = 4 * h + i;
            ulonglong2 w0 = *(const ulonglong2*)&sW[r][x * 8];
            ulonglong2 w1 = *(const ulonglong2*)&sW[r][x * 8 + 4];
            A2[i][0] = fma2(ad, w0.x, A2[i][0]);
            A2[i][1] = fma2(ad, w0.y, A2[i][1]);
            A2[i][2] = fma2(ad, w1.x, A2[i][2]);
            A2[i][3] = fma2(ad, w1.y, A2[i][3]);
        }
    }

    // ---- inf-norm over full matrix (combine partner halves)
    const ull ABSM = 0x7fffffff7fffffffULL;
    float nrm = 0.f;
#pragma unroll
    for (int i = 0; i < 4; i++) {
        ull s2 = A2[i][0] & ABSM;
        s2 = add2(s2, A2[i][1] & ABSM);
        s2 = add2(s2, A2[i][2] & ABSM);
        s2 = add2(s2, A2[i][3] & ABSM);
        float lo, hi; upk2(lo, hi, s2);
        nrm = fmaxf(nrm, lo + hi);
    }
    nrm = fmaxf(nrm, __shfl_xor_sync(0xffffffffu, nrm, 1));

    int s = 0;
    if (nrm > 0.25f) {
        s = (int)ceilf(log2f(nrm * 4.0f));
        if (s < 0) s = 0;
        if (s > 12) s = 12;
    }
    float sc = exp2f((float)(-s));
    ull scd = pk2(sc, sc);
#pragma unroll
    for (int i = 0; i < 4; i++)
#pragma unroll
        for (int jp = 0; jp < 4; jp++) A2[i][jp] = mul2(A2[i][jp], scd);

    // ---- Taylor-6 Horner: S = I + A/6 ; S = I + (A*S)/c, c=5..1
    ull S2[4][4], T2[4][4];
    {
        ull c6 = pk2(1.0f / 6.0f, 1.0f / 6.0f);
#pragma unroll
        for (int i = 0; i < 4; i++)
#pragma unroll
            for (int jp = 0; jp < 4; jp++) S2[i][jp] = mul2(A2[i][jp], c6);
        addI(S2, h);
    }
    const float invc[5] = {0.2f, 0.25f, 1.0f / 3.0f, 0.5f, 1.0f};
#pragma unroll
    for (int c = 0; c < 5; c++) {
        mm8h(T2, A2, S2, h);
        ull ic = pk2(invc[c], invc[c]);
#pragma unroll
        for (int i = 0; i < 4; i++)
#pragma unroll
            for (int jp = 0; jp < 4; jp++) S2[i][jp] = mul2(T2[i][jp], ic);
        addI(S2, h);
    }

    // ---- squarings (warp-uniform trip count, per-pair predicated commit)
    int smax = __reduce_max_sync(0xffffffffu, s);
    for (int q = 0; q < smax; q++) {
        mm8h(T2, S2, S2, h);
        if (q < s) {
#pragma unroll
            for (int i = 0; i < 4; i++)
#pragma unroll
                for (int jp = 0; jp < 4; jp++) S2[i][jp] = T2[i][jp];
        }
    }

    // ---- emit M = S^T : I own S rows 4h..4h+3 = M columns 4h..4h+3
    float Sf[4][8];
#pragma unroll
    for (int i = 0; i < 4; i++)
#pragma unroll
        for (int jp = 0; jp < 4; jp++)
            upk2(Sf[i][2 * jp], Sf[i][2 * jp + 1], S2[i][jp]);

    float* dstb = rho + (size_t)bt * (LATD * LATD) + (size_t)(kb * 8) * LATD + kb * 8 + 4 * h;
    float* dstc = g_compact + (size_t)bt * 512 + kb * 64 + 4 * h;
#pragma unroll
    for (int i = 0; i < 8; i++) {
        float4 v = make_float4(Sf[0][i], Sf[1][i], Sf[2][i], Sf[3][i]);
        *(float4*)&dstb[(size_t)i * LATD] = v;
        *(float4*)&dstc[i * 8]            = v;
    }

    // ---- zeros for this CTA's row-stripe: rows kb*8..kb*8+7 of each pair,
    //      all float4 columns except the diagonal block (disjoint addresses)
    float4 z = make_float4(0.f, 0.f, 0.f, 0.f);
    for (int f = tid; f < 64 * 128; f += 128) {
        int q   = f >> 7;           // pair 0..63
        int rem = f & 127;          // row*16 + c4
        int row = rem >> 4, c4 = rem & 15;
        if ((c4 >> 1) != kb)
            ((float4*)(rho + (size_t)(bt0 + q) * (LATD * LATD)
                           + (size_t)(kb * 8 + row) * LATD))[c4] = z;
    }
}

// ---------------------------------------------------------------------------
// Sequential scan over compact blocks: 512 chains of 8-dim vec-mat steps.
// 128 CTAs x 32 threads: CTA = (b, kb-half); 8 threads per chain.
// ---------------------------------------------------------------------------
__global__ __launch_bounds__(32) void scan_kernel(
    const float* __restrict__ latent, float* __restrict__ predLat)
{
    int b    = blockIdx.x >> 1;
    int half = blockIdx.x & 1;
    int sub  = threadIdx.x;          // 0..31
    int kb   = (sub >> 3) + half * 4;
    int j    = sub & 7;
    int grp  = sub & 24;
    int e    = kb * 8 + j;           // element index in 64-vector

    const float* mbase = g_compact + (size_t)b * TA * 512 + kb * 64 + j;
    float h = latent[(size_t)b * TT * LATD + e];
    predLat[(size_t)b * TT * LATD + e] = h;

    float b0[8], b1[8], b2[8], b3[8];

#define LDBUF(buf, t) { const float* pp = mbase + (size_t)(t) * 512; \
    _Pragma("unroll") for (int i = 0; i < 8; i++) buf[i] = pp[i * 8]; }

#define STEPH(buf, t) { float hn = 0.f; \
    _Pragma("unroll") for (int i = 0; i < 8; i++) { \
        float hv = __shfl_sync(0xffffffffu, h, grp + i); \
        hn = fmaf(hv, buf[i], hn); } \
    h = hn; \
    predLat[(size_t)(b * TT + (t) + 1) * LATD + e] = h; }

    LDBUF(b0, 0); LDBUF(b1, 1); LDBUF(b2, 2); LDBUF(b3, 3);
    int t = 0;
    for (int it = 0; it < 62; it++) {
        STEPH(b0, t); LDBUF(b0, t + 4); t++;
        STEPH(b1, t); LDBUF(b1, t + 4); t++;
        STEPH(b2, t); LDBUF(b2, t + 4); t++;
        STEPH(b3, t); LDBUF(b3, t + 4); t++;
    }
    STEPH(b0, 248); LDBUF(b0, 252);
    STEPH(b1, 249); LDBUF(b1, 253);
    STEPH(b2, 250); LDBUF(b2, 254);
    STEPH(b3, 251);
    STEPH(b0, 252);
    STEPH(b1, 253);
    STEPH(b2, 254);
#undef LDBUF
#undef STEPH
}

// ---------------------------------------------------------------------------
extern "C" void kernel_launch(void* const* d_in, const int* in_sizes, int n_in,
                              void* d_out, int out_size)
{
    (void)in_sizes; (void)n_in; (void)out_size;
    const float* obs  = (const float*)d_in[0];
    const float* acts = (const float*)d_in[1];
    const float* Wenc = (const float*)d_in[2];
    const float* benc = (const float*)d_in[3];
    const float* Wdec = (const float*)d_in[4];
    const float* bdec = (const float*)d_in[5];
    const float* Wphi = (const float*)d_in[6];
    const float* bphi = (const float*)d_in[7];

    float* out    = (float*)d_out;
    float* latent = out;
    float* rho    = out + OFF_RHO;
    float* predL  = out + OFF_PL;
    float* predO  = out + OFF_PO;

    // 1. latent_obs = obs @ W_enc + b_enc   (16384 x 64, K=512)
    gemm_bias_kernel<64><<<dim3(1, 128), 128>>>(obs, Wenc, benc, latent,
                                                BB * TT, LATD, OBSD);
    // 2. rho blocks (phi GEMM + expm), zeros, compact scratch (kb-split CTAs)
    phi_expm_kernel<<<dim3(NBT / 64, 8), 128>>>(acts, Wphi, bphi, rho);
    // 3. sequential latent scan over compact blocks
    scan_kernel<<<BB * 2, 32>>>(latent, predL);
    // 4. predicted_obs = predL @ W_dec + b_dec  (16384 x 512, K=64)
    gemm_bias_kernel<128><<<dim3(4, 128), 256>>>(predL, Wdec, bdec, predO,
                                                 BB * TT, PHID, LATD);
}